// round 1
// baseline (speedup 1.0000x reference)
#include <cuda_runtime.h>
#include <cstdint>

#define NB 16
#define NC 64
#define NT 2048
#define KNN 3

// scratch (static __device__ arrays: allocation-free per harness rules)
__device__ float g_nsq[NB * NT];
__device__ int   g_idx[NB * NT * KNN];

// ---------------- f32x2 helpers (sm_100+ packed fp32 FMA: full-rate 128 FMA/cyc/SM) ----
__device__ __forceinline__ unsigned long long dup2(float v) {
    unsigned long long r;
    asm("mov.b64 %0, {%1, %1};" : "=l"(r) : "f"(v));
    return r;
}
__device__ __forceinline__ void fma2(unsigned long long& d, unsigned long long a, unsigned long long b) {
    asm("fma.rn.f32x2 %0, %1, %2, %0;" : "+l"(d) : "l"(a), "l"(b));
}
__device__ __forceinline__ void unpack2(unsigned long long v, float& lo, float& hi) {
    asm("mov.b64 {%0, %1}, %2;" : "=f"(lo), "=f"(hi) : "l"(v));
}

// ---------------- kernel 1: squared norms ------------------------------------------
__global__ void nsq_kernel(const float* __restrict__ x) {
    int tid = blockIdx.x * blockDim.x + threadIdx.x;   // NB*NT threads
    int b = tid >> 11;
    int t = tid & (NT - 1);
    const float* xp = x + ((size_t)b * NC) * NT + t;
    float s = 0.f;
#pragma unroll
    for (int c = 0; c < NC; c++) {
        float v = xp[(size_t)c * NT];
        s = fmaf(v, v, s);
    }
    g_nsq[tid] = s;
}

// ---------------- kernel 2: fused gram + top-3 -------------------------------------
// Block: 256 threads, tile 128 rows(t) x 128 cols(s), per-thread 4 rows x 16 cols
// (8 f32x2 pairs). Top-3 smallest score = nsq[s] - 2*dot kept in registers,
// merged across the 8 col-threads at the end. Tie-break: lower index (matches
// jax.lax.top_k stability).
extern __shared__ float smem[];

#define TK_INSERT(r, SC, SI)                                                       \
    do {                                                                           \
        float _sc = (SC); int _si = (SI);                                          \
        if (_sc < ts2[r] || (_sc == ts2[r] && _si < ti2[r])) {                     \
            ts2[r] = _sc; ti2[r] = _si;                                            \
            if (ts2[r] < ts1[r] || (ts2[r] == ts1[r] && ti2[r] < ti1[r])) {        \
                float _t = ts1[r]; ts1[r] = ts2[r]; ts2[r] = _t;                   \
                int _i = ti1[r]; ti1[r] = ti2[r]; ti2[r] = _i;                     \
                if (ts1[r] < ts0[r] || (ts1[r] == ts0[r] && ti1[r] < ti0[r])) {    \
                    _t = ts0[r]; ts0[r] = ts1[r]; ts1[r] = _t;                     \
                    _i = ti0[r]; ti0[r] = ti1[r]; ti1[r] = _i;                     \
                }                                                                  \
            }                                                                      \
        }                                                                          \
    } while (0)

__global__ __launch_bounds__(256) void topk_kernel(const float* __restrict__ x) {
    const int b  = blockIdx.y;
    const int t0 = blockIdx.x * 128;
    float* At   = smem;                 // [64][128]
    float* Bs   = smem + 64 * 128;      // [64][128]
    float* snsq = smem + 2 * 64 * 128;  // [128]

    const int tid = threadIdx.x;
    const int tx  = tid & 7;    // s-group (covers s-pairs tx + 8p, p=0..7)
    const int ty  = tid >> 3;   // row-group: rows ty*4 .. ty*4+3

    const float* xb = x + (size_t)b * NC * NT;

    // load A tile (rows t0..t0+127, all 64 channels), coalesced
    for (int i = tid; i < 64 * 128; i += 256) {
        int c = i >> 7, tl = i & 127;
        At[i] = xb[(size_t)c * NT + t0 + tl];
    }

    float ts0[4], ts1[4], ts2[4];
    int   ti0[4], ti1[4], ti2[4];
#pragma unroll
    for (int r = 0; r < 4; r++) {
        ts0[r] = ts1[r] = ts2[r] = 3.4e38f;
        ti0[r] = ti1[r] = ti2[r] = 0x7fffffff;
    }

    const unsigned long long m2 = dup2(-2.0f);

    for (int s0 = 0; s0 < NT; s0 += 128) {
        __syncthreads();  // protects At on first iter, Bs/snsq reuse afterwards
        for (int i = tid; i < 64 * 128; i += 256) {
            int c = i >> 7, tl = i & 127;
            Bs[i] = xb[(size_t)c * NT + s0 + tl];
        }
        if (tid < 128) snsq[tid] = g_nsq[b * NT + s0 + tid];
        __syncthreads();

        unsigned long long acc[4][8];
#pragma unroll
        for (int r = 0; r < 4; r++)
#pragma unroll
            for (int p = 0; p < 8; p++) acc[r][p] = 0ull;

#pragma unroll 8
        for (int c = 0; c < 64; c++) {
            float4 a4 = *(const float4*)&At[c * 128 + ty * 4];
            unsigned long long ad0 = dup2(a4.x), ad1 = dup2(a4.y);
            unsigned long long ad2 = dup2(a4.z), ad3 = dup2(a4.w);
            const unsigned long long* bp = (const unsigned long long*)&Bs[c * 128];
            unsigned long long b2[8];
#pragma unroll
            for (int p = 0; p < 8; p++) b2[p] = bp[tx + 8 * p];  // conflict-free: 64B run
#pragma unroll
            for (int p = 0; p < 8; p++) {
                fma2(acc[0][p], ad0, b2[p]);
                fma2(acc[1][p], ad1, b2[p]);
                fma2(acc[2][p], ad2, b2[p]);
                fma2(acc[3][p], ad3, b2[p]);
            }
        }

        // score = nsq[s] - 2*dot, fold into per-thread top-3
        const unsigned long long* np = (const unsigned long long*)snsq;
#pragma unroll
        for (int p = 0; p < 8; p++) {
            unsigned long long n2 = np[tx + 8 * p];
            int sbase = s0 + 2 * (tx + 8 * p);
#pragma unroll
            for (int r = 0; r < 4; r++) {
                unsigned long long sc2 = n2;
                fma2(sc2, m2, acc[r][p]);   // nsq - 2*dot (packed pair)
                float lo, hi;
                unpack2(sc2, lo, hi);
                TK_INSERT(r, lo, sbase);
                TK_INSERT(r, hi, sbase + 1);
            }
        }
    }

    // merge the 8 col-thread candidate lists per row (24 candidates -> top-3)
    __syncthreads();
    float* msc = smem;                    // [128][24]
    int*   mix = (int*)(smem + 128 * 24); // [128][24]
#pragma unroll
    for (int r = 0; r < 4; r++) {
        int row  = ty * 4 + r;
        int base = (row * 8 + tx) * 3;
        msc[base + 0] = ts0[r]; mix[base + 0] = ti0[r];
        msc[base + 1] = ts1[r]; mix[base + 1] = ti1[r];
        msc[base + 2] = ts2[r]; mix[base + 2] = ti2[r];
    }
    __syncthreads();
    if (tid < 128) {
        float bs0 = 3.4e38f, bs1 = 3.4e38f, bs2 = 3.4e38f;
        int   bi0 = 0x7fffffff, bi1 = 0x7fffffff, bi2 = 0x7fffffff;
#pragma unroll
        for (int e = 0; e < 24; e++) {
            float sc = msc[tid * 24 + e];
            int   si = mix[tid * 24 + e];
            if (sc < bs2 || (sc == bs2 && si < bi2)) {
                bs2 = sc; bi2 = si;
                if (bs2 < bs1 || (bs2 == bs1 && bi2 < bi1)) {
                    float t_ = bs1; bs1 = bs2; bs2 = t_;
                    int i_ = bi1; bi1 = bi2; bi2 = i_;
                    if (bs1 < bs0 || (bs1 == bs0 && bi1 < bi0)) {
                        t_ = bs0; bs0 = bs1; bs1 = t_;
                        i_ = bi0; bi0 = bi1; bi1 = i_;
                    }
                }
            }
        }
        int g = (b * NT + t0 + tid) * KNN;
        g_idx[g + 0] = bi0;
        g_idx[g + 1] = bi1;
        g_idx[g + 2] = bi2;
    }
}

// ---------------- kernel 3: fused gather + conv (64x192 GEMM per t-tile) -----------
// out[b,o,t] = bias[o] + sum_j W[o*192+j] * x[b, j/3, idx[b,t,j%3]]
__global__ __launch_bounds__(256) void conv_kernel(const float* __restrict__ x,
                                                   const float* __restrict__ W,
                                                   const float* __restrict__ bias,
                                                   float* __restrict__ out) {
    const int b  = blockIdx.y;
    const int t0 = blockIdx.x * 128;
    float* Ws   = smem;                        // [192][64] transposed: Ws[j][o]
    float* ps   = smem + 192 * 64;             // [64][128] gathered prime chunk
    int*   sidx = (int*)(smem + 192 * 64 + 64 * 128);  // [128*3]

    const int tid = threadIdx.x;
    for (int i = tid; i < 192 * 64; i += 256) {
        int j = i >> 6, o = i & 63;
        Ws[i] = W[o * 192 + j];
    }
    for (int i = tid; i < 128 * KNN; i += 256)
        sidx[i] = g_idx[(b * NT + t0) * KNN + i];

    const int to = tid & 15;   // o-group: o = to*4 .. +3
    const int tt = tid >> 4;   // t-group: t = tt*8 .. +7
    float acc[4][8];
#pragma unroll
    for (int r = 0; r < 4; r++)
#pragma unroll
        for (int e = 0; e < 8; e++) acc[r][e] = 0.f;

    const float* xb = x + (size_t)b * NC * NT;

    for (int jc = 0; jc < 3; jc++) {
        __syncthreads();  // Ws/sidx ready (first), ps free (later)
        for (int i = tid; i < 64 * 128; i += 256) {
            int jj = i >> 7, tl = i & 127;
            int j  = jc * 64 + jj;
            int ch = j / 3;
            int kk = j - ch * 3;
            ps[i] = xb[(size_t)ch * NT + sidx[tl * KNN + kk]];  // L2-resident gather
        }
        __syncthreads();
#pragma unroll 8
        for (int jj = 0; jj < 64; jj++) {
            float4 w4 = *(const float4*)&Ws[(jc * 64 + jj) * 64 + to * 4];
            float4 p0 = *(const float4*)&ps[jj * 128 + tt * 8];
            float4 p1 = *(const float4*)&ps[jj * 128 + tt * 8 + 4];
            float pv[8] = {p0.x, p0.y, p0.z, p0.w, p1.x, p1.y, p1.z, p1.w};
            float wv[4] = {w4.x, w4.y, w4.z, w4.w};
#pragma unroll
            for (int r = 0; r < 4; r++)
#pragma unroll
                for (int e = 0; e < 8; e++)
                    acc[r][e] = fmaf(wv[r], pv[e], acc[r][e]);
        }
    }

#pragma unroll
    for (int r = 0; r < 4; r++) {
        int o = to * 4 + r;
        float bo = __ldg(&bias[o]);
        float* op = out + ((size_t)(b * NC + o)) * NT + t0 + tt * 8;
#pragma unroll
        for (int e = 0; e < 8; e++) op[e] = acc[r][e] + bo;
    }
}

// ---------------- launch -----------------------------------------------------------
extern "C" void kernel_launch(void* const* d_in, const int* in_sizes, int n_in,
                              void* d_out, int out_size) {
    const float* x    = (const float*)d_in[0];
    const float* W    = (const float*)d_in[1];
    const float* bias = (const float*)d_in[2];
    float* out        = (float*)d_out;

    const int topk_smem = (2 * 64 * 128 + 128) * 4;                 // 66048 B
    const int conv_smem = (192 * 64 + 64 * 128 + 0) * 4 + 128 * KNN * 4;  // 83456 B
    cudaFuncSetAttribute(topk_kernel, cudaFuncAttributeMaxDynamicSharedMemorySize, topk_smem);
    cudaFuncSetAttribute(conv_kernel, cudaFuncAttributeMaxDynamicSharedMemorySize, conv_smem);

    nsq_kernel<<<(NB * NT) / 256, 256>>>(x);
    topk_kernel<<<dim3(NT / 128, NB), 256, topk_smem>>>(x);
    conv_kernel<<<dim3(NT / 128, NB), 256, conv_smem>>>(x, W, bias, out);
}

// round 4
// speedup vs baseline: 1.6199x; 1.6199x over previous
#include <cuda_runtime.h>
#include <cstdint>

#define NB 16
#define NC 64
#define NT 2048
#define KNN 3
#define NTILE 16      // NT/128
#define NPAIR 136     // NTILE*(NTILE+1)/2

// scratch (static __device__ arrays: allocation-free per harness rules)
__device__ float g_nsq[NB * NT];
__device__ float g_cs[(size_t)NB * NT * NTILE * KNN];  // candidate scores
__device__ int   g_ci[(size_t)NB * NT * NTILE * KNN];  // candidate indices

// ---------------- f32x2 helpers (sm_100+ packed fp32 FMA) --------------------------
__device__ __forceinline__ unsigned long long dup2(float v) {
    unsigned long long r;
    asm("mov.b64 %0, {%1, %1};" : "=l"(r) : "f"(v));
    return r;
}
__device__ __forceinline__ void fma2(unsigned long long& d, unsigned long long a, unsigned long long b) {
    asm("fma.rn.f32x2 %0, %1, %2, %0;" : "+l"(d) : "l"(a), "l"(b));
}

// top-3 insert with (score, index) lexicographic tie-break (== lax.top_k stability)
#define INS3(SC, SI)                                                          \
    do {                                                                      \
        float _s = (SC); int _i = (SI);                                       \
        if (_s < q2 || (_s == q2 && _i < j2)) {                               \
            q2 = _s; j2 = _i;                                                 \
            if (q2 < q1 || (q2 == q1 && j2 < j1)) {                           \
                float _t = q1; q1 = q2; q2 = _t;                              \
                int _k = j1; j1 = j2; j2 = _k;                                \
                if (q1 < q0 || (q1 == q0 && j1 < j0)) {                       \
                    _t = q0; q0 = q1; q1 = _t;                                \
                    _k = j0; j0 = j1; j1 = _k;                                \
                }                                                             \
            }                                                                 \
        }                                                                     \
    } while (0)

// ---------------- kernel 1: squared norms (2-way channel split + shfl) -------------
__global__ void nsq_kernel(const float* __restrict__ x) {
    int gid = blockIdx.x * blockDim.x + threadIdx.x;   // 2*NB*NT threads
    int half = gid & 1;
    int t = (gid >> 1) & (NT - 1);
    int b = gid >> 12;
    const float* xp = x + ((size_t)(b * NC + half * 32)) * NT + t;
    float s = 0.f;
#pragma unroll
    for (int c = 0; c < 32; c++) {
        float v = xp[(size_t)c * NT];
        s = fmaf(v, v, s);
    }
    s += __shfl_xor_sync(0xffffffffu, s, 1);
    if (!half) g_nsq[b * NT + t] = s;
}

// ---------------- kernel 2: symmetric gram tile + bidirectional top-3 --------------
// One block per (ti, tj) tile-pair with tj >= ti. Computes the 128x128 dot tile,
// stores it to smem, then 128 threads scan rows (candidates for t-rows, slot tj)
// and 128 threads scan columns (candidates for s-rows, slot ti; skipped on diag).
extern __shared__ float smem[];

__global__ __launch_bounds__(256) void gram_kernel(const float* __restrict__ x) {
    const int b = blockIdx.y;
    // closed-form upper-triangle decode: p -> (ti, tj), tj >= ti
    {
    }
    const int p  = blockIdx.x;
    // ti = smallest i with p < sum_{u<=i}(NTILE-u); use float sqrt then fix up
    int ti = (int)(NTILE + 0.5f - sqrtf((NTILE + 0.5f) * (NTILE + 0.5f) - 2.0f * p));
    int off = ti * NTILE - (ti * (ti - 1)) / 2;
    if (p < off)               { ti--; off = ti * NTILE - (ti * (ti - 1)) / 2; }
    else if (p >= off + NTILE - ti) { ti++; off = ti * NTILE - (ti * (ti - 1)) / 2; }
    const int tj = ti + (p - off);
    const int t0 = ti * 128, s0 = tj * 128;

    float* At    = smem;                  // [64][128]   (phase 1)
    float* Bs    = smem + 64 * 128;       // [64][128]   (phase 1)
    float* score = smem;                  // [128][132]  (phase 2, overlays At/Bs)
    float* nsqR  = smem + 128 * 132;      // [128]
    float* nsqC  = nsqR + 128;            // [128]

    const int tid = threadIdx.x;
    const int tx  = tid & 7;    // s-pair group: pairs tx + 8p
    const int ty  = tid >> 3;   // row group: rows ty*4 .. +3

    const float*  xb  = x + (size_t)b * NC * NT;
    const float4* xb4 = (const float4*)xb;

#pragma unroll
    for (int i = tid; i < 2048; i += 256)
        ((float4*)At)[i] = xb4[(i >> 5) * (NT / 4) + (t0 >> 2) + (i & 31)];
#pragma unroll
    for (int i = tid; i < 2048; i += 256)
        ((float4*)Bs)[i] = xb4[(i >> 5) * (NT / 4) + (s0 >> 2) + (i & 31)];
    if (tid < 128) nsqR[tid] = g_nsq[b * NT + t0 + tid];
    else           nsqC[tid - 128] = g_nsq[b * NT + s0 + tid - 128];
    __syncthreads();

    unsigned long long acc[4][8];
#pragma unroll
    for (int r = 0; r < 4; r++)
#pragma unroll
        for (int q = 0; q < 8; q++) acc[r][q] = 0ull;

#pragma unroll 8
    for (int c = 0; c < 64; c++) {
        float4 a4 = *(const float4*)&At[c * 128 + ty * 4];
        unsigned long long ad0 = dup2(a4.x), ad1 = dup2(a4.y);
        unsigned long long ad2 = dup2(a4.z), ad3 = dup2(a4.w);
        const unsigned long long* bq = (const unsigned long long*)&Bs[c * 128];
        unsigned long long bv[8];
#pragma unroll
        for (int q = 0; q < 8; q++) bv[q] = bq[tx + 8 * q];   // 4-way broadcast, no conflict
#pragma unroll
        for (int q = 0; q < 8; q++) {
            fma2(acc[0][q], ad0, bv[q]);
            fma2(acc[1][q], ad1, bv[q]);
            fma2(acc[2][q], ad2, bv[q]);
            fma2(acc[3][q], ad3, bv[q]);
        }
    }
    __syncthreads();   // all LDS of At/Bs done before score overlays them

    // dump dot tile: STS.64, conflict-free (132 = 4 mod 16 padding)
#pragma unroll
    for (int r = 0; r < 4; r++)
#pragma unroll
        for (int q = 0; q < 8; q++)
            *(unsigned long long*)&score[(ty * 4 + r) * 132 + 2 * (tx + 8 * q)] = acc[r][q];
    __syncthreads();

    if (tid < 128) {
        // row scan: candidates for row t0+tid over s in [s0, s0+128)
        float q0 = 3.4e38f, q1 = 3.4e38f, q2 = 3.4e38f;
        int   j0 = 0x7fffffff, j1 = 0x7fffffff, j2 = 0x7fffffff;
        const float* rowp = &score[tid * 132];
        for (int i = 0; i < 128; i++) {
            int jj = (i + tid) & 127;                       // skew: conflict-free
            float sc = fmaf(-2.f, rowp[jj], nsqC[jj]);
            INS3(sc, s0 + jj);
        }
        size_t base = ((size_t)(b * NT + t0 + tid) * NTILE + tj) * KNN;
        g_cs[base + 0] = q0; g_ci[base + 0] = j0;
        g_cs[base + 1] = q1; g_ci[base + 1] = j1;
        g_cs[base + 2] = q2; g_ci[base + 2] = j2;
    } else if (ti != tj) {
        // column scan: candidates for row s0+cc over t in [t0, t0+128)
        int cc = tid - 128;
        float q0 = 3.4e38f, q1 = 3.4e38f, q2 = 3.4e38f;
        int   j0 = 0x7fffffff, j1 = 0x7fffffff, j2 = 0x7fffffff;
        for (int i = 0; i < 128; i++) {
            int jj = (i + cc) & 127;
            float sc = fmaf(-2.f, score[jj * 132 + cc], nsqR[jj]);
            INS3(sc, t0 + jj);
        }
        size_t base = ((size_t)(b * NT + s0 + cc) * NTILE + ti) * KNN;
        g_cs[base + 0] = q0; g_ci[base + 0] = j0;
        g_cs[base + 1] = q1; g_ci[base + 1] = j1;
        g_cs[base + 2] = q2; g_ci[base + 2] = j2;
    }
}

// ---------------- kernel 3: candidate merge + gather + conv ------------------------
// out[b,o,t] = bias[o] + sum_j W[o*192+j] * x[b, j/3, idx[b,t,j%3]]
__global__ __launch_bounds__(256) void conv_kernel(const float* __restrict__ x,
                                                   const float* __restrict__ W,
                                                   const float* __restrict__ bias,
                                                   float* __restrict__ out) {
    const int b  = blockIdx.y;
    const int t0 = blockIdx.x * 128;
    float* Ws   = smem;                                 // [192][64] transposed
    float* ps   = smem + 192 * 64;                      // [64][128] gathered chunk
    int*   sidx = (int*)(smem + 192 * 64 + 64 * 128);   // [128*3]

    const int tid = threadIdx.x;
    for (int i = tid; i < 192 * 64; i += 256) {
        int j = i >> 6, o = i & 63;
        Ws[i] = W[o * 192 + j];
    }
    // merge this block's 128 rows: 16 slots x 3 candidates -> final top-3
    if (tid < 128) {
        size_t cb = (size_t)(b * NT + t0 + tid) * (NTILE * KNN);
        float q0 = 3.4e38f, q1 = 3.4e38f, q2 = 3.4e38f;
        int   j0 = 0x7fffffff, j1 = 0x7fffffff, j2 = 0x7fffffff;
#pragma unroll 8
        for (int e = 0; e < NTILE * KNN; e++) {
            float sc = g_cs[cb + e];
            int   si = g_ci[cb + e];
            INS3(sc, si);
        }
        sidx[tid * KNN + 0] = j0;
        sidx[tid * KNN + 1] = j1;
        sidx[tid * KNN + 2] = j2;
    }

    const int to = tid & 15;   // o-group: o = to*4 .. +3
    const int tt = tid >> 4;   // t-group: t = tt*8 .. +7
    float acc[4][8];
#pragma unroll
    for (int r = 0; r < 4; r++)
#pragma unroll
        for (int e = 0; e < 8; e++) acc[r][e] = 0.f;

    const float* xb = x + (size_t)b * NC * NT;

    for (int jc = 0; jc < 3; jc++) {
        __syncthreads();  // Ws/sidx ready (first), ps free (later)
        for (int i = tid; i < 64 * 128; i += 256) {
            int jj = i >> 7, tl = i & 127;
            int j  = jc * 64 + jj;
            int ch = j / 3;
            int kk = j - ch * 3;
            ps[i] = xb[(size_t)ch * NT + sidx[tl * KNN + kk]];  // L2-resident gather
        }
        __syncthreads();
#pragma unroll 8
        for (int jj = 0; jj < 64; jj++) {
            float4 w4 = *(const float4*)&Ws[(jc * 64 + jj) * 64 + to * 4];
            float4 p0 = *(const float4*)&ps[jj * 128 + tt * 8];
            float4 p1 = *(const float4*)&ps[jj * 128 + tt * 8 + 4];
            float pv[8] = {p0.x, p0.y, p0.z, p0.w, p1.x, p1.y, p1.z, p1.w};
            float wv[4] = {w4.x, w4.y, w4.z, w4.w};
#pragma unroll
            for (int r = 0; r < 4; r++)
#pragma unroll
                for (int e = 0; e < 8; e++)
                    acc[r][e] = fmaf(wv[r], pv[e], acc[r][e]);
        }
    }

#pragma unroll
    for (int r = 0; r < 4; r++) {
        int o = to * 4 + r;
        float bo = __ldg(&bias[o]);
        float* op = out + ((size_t)(b * NC + o)) * NT + t0 + tt * 8;
#pragma unroll
        for (int e = 0; e < 8; e++) op[e] = acc[r][e] + bo;
    }
}

// ---------------- launch -----------------------------------------------------------
extern "C" void kernel_launch(void* const* d_in, const int* in_sizes, int n_in,
                              void* d_out, int out_size) {
    const float* x    = (const float*)d_in[0];
    const float* W    = (const float*)d_in[1];
    const float* bias = (const float*)d_in[2];
    float* out        = (float*)d_out;

    const int gram_smem = (128 * 132 + 256) * 4;                          // 68608 B
    const int conv_smem = (192 * 64 + 64 * 128 + 128 * KNN) * 4;          // 83456 B
    cudaFuncSetAttribute(gram_kernel, cudaFuncAttributeMaxDynamicSharedMemorySize, gram_smem);
    cudaFuncSetAttribute(conv_kernel, cudaFuncAttributeMaxDynamicSharedMemorySize, conv_smem);

    nsq_kernel<<<(2 * NB * NT) / 256, 256>>>(x);
    gram_kernel<<<dim3(NPAIR, NB), 256, gram_smem>>>(x);
    conv_kernel<<<dim3(NT / 128, NB), 256, conv_smem>>>(x, W, bias, out);
}